// round 9
// baseline (speedup 1.0000x reference)
#include <cuda_runtime.h>
#include <cstdint>

// Problem constants
#define NN 50000
#define EE 800000
#define ET (EE + NN)          // edges + fresh self loops
#define HEADS 8
#define F 256                 // HEADS * 32 (same for both layers)
#define SCAN_T 1024
#define SCAN_CH ((NN + SCAN_T - 1) / SCAN_T)   // 49

typedef unsigned long long ull;

// ---------------- scratch (device globals; no allocation) ----------------
__device__ __align__(16) float g_xl[(size_t)NN * F];   // lin_l(x)  [N,256]
__device__ __align__(16) float g_xr[(size_t)NN * F];   // lin_r(x)  [N,256]
__device__ __align__(16) float g_h[NN * 32];           // layer-1 output
__device__ int g_deg[NN];     // in-degree (incl. self loop)
__device__ int g_off[NN];     // CSR row start (exclusive scan of deg)
__device__ int g_pos[NN];     // fill cursor
__device__ int g_csr[ET];     // src node per CSR slot

#define NEG_INF (-__int_as_float(0x7f800000))

// ---------------- packed f32x2 helpers (sm_100+) ----------------
__device__ __forceinline__ ull pk2(float lo, float hi) {
    ull r;
    asm("mov.b64 %0, {%1, %2};" : "=l"(r)
        : "r"(__float_as_uint(lo)), "r"(__float_as_uint(hi)));
    return r;
}
__device__ __forceinline__ void upk2(ull v, float& lo, float& hi) {
    unsigned a, b;
    asm("mov.b64 {%0, %1}, %2;" : "=r"(a), "=r"(b) : "l"(v));
    lo = __uint_as_float(a); hi = __uint_as_float(b);
}
__device__ __forceinline__ ull add2(ull a, ull b) {
    ull r; asm("add.rn.f32x2 %0, %1, %2;" : "=l"(r) : "l"(a), "l"(b)); return r;
}
__device__ __forceinline__ ull mul2(ull a, ull b) {
    ull r; asm("mul.rn.f32x2 %0, %1, %2;" : "=l"(r) : "l"(a), "l"(b)); return r;
}
__device__ __forceinline__ ull fma2(ull a, ull b, ull c) {
    ull r; asm("fma.rn.f32x2 %0, %1, %2, %3;" : "=l"(r) : "l"(a), "l"(b), "l"(c)); return r;
}
#define ABS2_MASK 0x7FFFFFFF7FFFFFFFULL

// ---------------- CSR build (graph identical for both layers) ----------------
__global__ void deg_init_kernel() {
    int i = blockIdx.x * blockDim.x + threadIdx.x;
    if (i < NN) g_deg[i] = 1;                 // fresh self loop
}

__global__ void deg_count_kernel(const int* __restrict__ ei) {
    int e = blockIdx.x * blockDim.x + threadIdx.x;
    if (e >= EE) return;
    int s = ei[e], d = ei[EE + e];
    if (s != d) atomicAdd(&g_deg[d], 1);      // original self loops masked
}

// single-block exclusive scan of g_deg -> g_off, g_pos
__global__ __launch_bounds__(SCAN_T) void scan_kernel() {
    __shared__ int sh[SCAN_T];
    int t = threadIdx.x;
    int base = t * SCAN_CH;
    int sum = 0;
#pragma unroll 4
    for (int j = 0; j < SCAN_CH; j++) {
        int idx = base + j;
        if (idx < NN) sum += g_deg[idx];
    }
    sh[t] = sum;
    __syncthreads();
    for (int ofs = 1; ofs < SCAN_T; ofs <<= 1) {
        int v = (t >= ofs) ? sh[t - ofs] : 0;
        __syncthreads();
        sh[t] += v;
        __syncthreads();
    }
    int run = sh[t] - sum;                    // exclusive prefix for this chunk
    for (int j = 0; j < SCAN_CH; j++) {
        int idx = base + j;
        if (idx < NN) {
            g_off[idx] = run;
            g_pos[idx] = run;
            run += g_deg[idx];
        }
    }
}

__global__ void csr_fill_kernel(const int* __restrict__ ei) {
    int e = blockIdx.x * blockDim.x + threadIdx.x;
    if (e >= ET) return;
    int s, d;
    if (e < EE) {
        s = ei[e]; d = ei[EE + e];
        if (s == d) return;                   // masked original self loop
    } else {
        s = d = e - EE;                       // fresh self loop
    }
    int slot = atomicAdd(&g_pos[d], 1);
    g_csr[slot] = s;
}

// ---------------- fused GEMM: xl = x@Wl^T+bl, xr = x@Wr^T+br ----------------
template <int K>
__global__ __launch_bounds__(512) void gemm_kernel(
    const float* __restrict__ xin,   // nullptr -> use g_h
    const float* __restrict__ Wl, const float* __restrict__ bl,
    const float* __restrict__ Wr, const float* __restrict__ br)
{
    const int TILE = 32;
    __shared__ __align__(16) float xs[TILE * K];
    const float* x = xin ? xin : g_h;

    int t   = threadIdx.x;
    int col = t & 255;
    const float* W = (t < 256) ? Wl : Wr;
    float* o       = (t < 256) ? g_xl : g_xr;
    float w[K];
#pragma unroll
    for (int k = 0; k < K; k += 4) {
        float4 v = *(const float4*)(W + col * K + k);
        w[k] = v.x; w[k + 1] = v.y; w[k + 2] = v.z; w[k + 3] = v.w;
    }
    float bias = ((t < 256) ? bl : br)[col];

    for (int row0 = blockIdx.x * TILE; row0 < NN; row0 += gridDim.x * TILE) {
        int nr = min(TILE, NN - row0);
        __syncthreads();
        for (int i = t; i < nr * K; i += 512) xs[i] = x[row0 * K + i];
        __syncthreads();
        for (int r = 0; r < nr; r++) {
            float a0 = 0.f, a1 = 0.f, a2 = 0.f, a3 = 0.f;
            const float4* xp = (const float4*)(xs + r * K);
#pragma unroll
            for (int k = 0; k < K / 4; k++) {
                float4 xv = xp[k];
                a0 += xv.x * w[4 * k];     a1 += xv.y * w[4 * k + 1];
                a2 += xv.z * w[4 * k + 2]; a3 += xv.w * w[4 * k + 3];
            }
            o[(size_t)(row0 + r) * F + col] = (a0 + a1) + (a2 + a3) + bias;
        }
    }
}

// packed GATv2 score partial for one src row (4 packed channel-pairs)
__device__ __forceinline__ float score_of(const ull* l2, const ull* r2, const ull* at2,
                                          ull c06, ull c04)
{
    ull p2 = 0;
#pragma unroll
    for (int j = 0; j < 4; j++) {
        ull v  = add2(l2[j], r2[j]);
        ull av = v & ABS2_MASK;                       // |v| per lane
        ull lk = fma2(av, c04, mul2(v, c06));          // 0.6v + 0.4|v| == leaky(v,0.2)
        p2 = fma2(lk, at2[j], p2);
    }
    float pa, pb; upk2(p2, pa, pb);
    float p = pa + pb;
    // butterfly within 4-lane head group: every lane gets full head score
    p += __shfl_xor_sync(0xFFFFFFFFu, p, 1);
    p += __shfl_xor_sync(0xFFFFFFFFu, p, 2);
    return p;
}

// ---------------- fused per-node attention: warp per dst node ----------------
// Lane l owns channels [8l, 8l+8) == head (l>>2). Online softmax, 2-edge unrolled.
__global__ __launch_bounds__(256) void node_attn_kernel(
    const float* __restrict__ att, const float* __restrict__ bias,
    float* __restrict__ outp,      // nullptr -> g_h
    int act)
{
    int lane = threadIdx.x & 31;
    int node = (blockIdx.x * blockDim.x + threadIdx.x) >> 5;
    if (node >= NN) return;

    const ull c06 = pk2(0.6f, 0.6f);
    const ull c04 = pk2(0.4f, 0.4f);

    // att row for this lane's 8 channels (already pairwise-packed in memory)
    ulonglong2 atv0 = *((const ulonglong2*)att + lane * 2);
    ulonglong2 atv1 = *((const ulonglong2*)att + lane * 2 + 1);
    ull at2[4] = { atv0.x, atv0.y, atv1.x, atv1.y };

    // xr[dst] once per node
    const ulonglong2* pr = (const ulonglong2*)(g_xr + (size_t)node * F) + lane * 2;
    ulonglong2 rv0 = pr[0], rv1 = pr[1];
    ull r2[4] = { rv0.x, rv0.y, rv1.x, rv1.y };

    int beg = g_off[node];
    int end = beg + g_deg[node];

    float m = NEG_INF, denom = 0.f;
    ull ac2[4] = { 0, 0, 0, 0 };    // packed zeros (0x0 == {0.f,0.f})

    int k = beg;
    for (; k + 2 <= end; k += 2) {
        int s0 = __ldg(&g_csr[k]);
        int s1 = __ldg(&g_csr[k + 1]);
        const ulonglong2* pl0 = (const ulonglong2*)(g_xl + (size_t)s0 * F) + lane * 2;
        const ulonglong2* pl1 = (const ulonglong2*)(g_xl + (size_t)s1 * F) + lane * 2;
        ulonglong2 a0 = pl0[0], a1 = pl0[1];          // 4 independent 16B loads
        ulonglong2 b0 = pl1[0], b1 = pl1[1];
        ull l0[4] = { a0.x, a0.y, a1.x, a1.y };
        ull l1[4] = { b0.x, b0.y, b1.x, b1.y };

        float p0 = score_of(l0, r2, at2, c06, c04);
        float p1 = score_of(l1, r2, at2, c06, c04);

        float mn = fmaxf(m, fmaxf(p0, p1));
        float c  = __expf(m - mn);                    // 0 on first pair (m=-inf)
        float w0 = __expf(p0 - mn);
        float w1 = __expf(p1 - mn);
        denom = denom * c + (w0 + w1);
        ull cc = pk2(c, c), ww0 = pk2(w0, w0), ww1 = pk2(w1, w1);
#pragma unroll
        for (int j = 0; j < 4; j++)
            ac2[j] = fma2(l1[j], ww1, fma2(l0[j], ww0, mul2(ac2[j], cc)));
        m = mn;
    }
    if (k < end) {                                    // odd tail
        int s0 = __ldg(&g_csr[k]);
        const ulonglong2* pl0 = (const ulonglong2*)(g_xl + (size_t)s0 * F) + lane * 2;
        ulonglong2 a0 = pl0[0], a1 = pl0[1];
        ull l0[4] = { a0.x, a0.y, a1.x, a1.y };
        float p0 = score_of(l0, r2, at2, c06, c04);
        float mn = fmaxf(m, p0);
        float c  = __expf(m - mn);
        float w0 = __expf(p0 - mn);
        denom = denom * c + w0;
        ull cc = pk2(c, c), ww0 = pk2(w0, w0);
#pragma unroll
        for (int j = 0; j < 4; j++)
            ac2[j] = fma2(l0[j], ww0, mul2(ac2[j], cc));
    }

    float inv = __frcp_rn(fmaxf(denom, 1e-16f));
    float ac[8];
#pragma unroll
    for (int j = 0; j < 4; j++) upk2(ac2[j], ac[2 * j], ac[2 * j + 1]);
#pragma unroll
    for (int j = 0; j < 8; j++) {
        float v = ac[j] * inv;
        // sum over the 8 heads: lanes with equal (lane&3) hold distinct heads
        v += __shfl_xor_sync(0xFFFFFFFFu, v, 4);
        v += __shfl_xor_sync(0xFFFFFFFFu, v, 8);
        v += __shfl_xor_sync(0xFFFFFFFFu, v, 16);
        ac[j] = v;
    }

    if (lane < 4) {
        float* o = (outp ? outp : g_h) + (size_t)node * 32 + lane * 8;
#pragma unroll
        for (int j = 0; j < 8; j++) {
            float s = ac[j] * 0.125f + bias[lane * 8 + j];
            if (act && s < 0.f) s *= 0.01f;
            o[j] = s;
        }
    }
}

// ---------------- launch ----------------
extern "C" void kernel_launch(void* const* d_in, const int* in_sizes, int n_in,
                              void* d_out, int out_size)
{
    const float* x     = (const float*)d_in[0];
    const int*   ei    = (const int*)d_in[1];     // int32 (harness dtype set)
    const float* W1l   = (const float*)d_in[2];
    const float* b1l   = (const float*)d_in[3];
    const float* W1r   = (const float*)d_in[4];
    const float* b1r   = (const float*)d_in[5];
    const float* att1  = (const float*)d_in[6];
    const float* bias1 = (const float*)d_in[7];
    const float* W2l   = (const float*)d_in[8];
    const float* b2l   = (const float*)d_in[9];
    const float* W2r   = (const float*)d_in[10];
    const float* b2r   = (const float*)d_in[11];
    const float* att2  = (const float*)d_in[12];
    const float* bias2 = (const float*)d_in[13];
    float* out = (float*)d_out;

    const int NB  = (NN + 255) / 256;
    const int EB  = (EE + 255) / 256;
    const int TB  = (ET + 255) / 256;
    const int AB  = (NN * 32 + 255) / 256;    // warp/node: 8 nodes per 256-thr block

    // ---- CSR build (shared by both layers) ----
    deg_init_kernel<<<NB, 256>>>();
    deg_count_kernel<<<EB, 256>>>(ei);
    scan_kernel<<<1, SCAN_T>>>();
    csr_fill_kernel<<<TB, 256>>>(ei);

    // ---- layer 1 ----
    gemm_kernel<64><<<296, 512>>>(x, W1l, b1l, W1r, b1r);
    node_attn_kernel<<<AB, 256>>>(att1, bias1, nullptr, 1);   // -> g_h, leaky 0.01

    // ---- layer 2 ----
    gemm_kernel<32><<<296, 512>>>(nullptr, W2l, b2l, W2r, b2r);
    node_attn_kernel<<<AB, 256>>>(att2, bias2, out, 0);       // -> d_out
}